// round 14
// baseline (speedup 1.0000x reference)
#include <cuda_runtime.h>
#include <math.h>

#define B_ 4
#define T_ 1024
#define D_ 1024
#define H_ 16
#define HD 64

// -------- scratch (device globals: allocation-free rule) --------
__device__ float g_q[B_*H_*T_*HD];
__device__ float g_k[B_*H_*T_*HD];
__device__ float g_v[B_*H_*T_*HD];
__device__ float g_ctx[(size_t)B_*T_*D_];
__device__ float g_gate[B_*H_*T_];
__device__ float g_relb[H_*2048];   // per-head bias by relative position rp+1023

// -------- packed fp32 helpers (Blackwell f32x2 pipe) --------
typedef unsigned long long u64;
__device__ __forceinline__ u64 fma2(u64 a, u64 b, u64 c) {
    u64 d;
    asm("fma.rn.f32x2 %0, %1, %2, %3;" : "=l"(d) : "l"(a), "l"(b), "l"(c));
    return d;
}
__device__ __forceinline__ u64 mul2(u64 a, u64 b) {
    u64 d;
    asm("mul.rn.f32x2 %0, %1, %2;" : "=l"(d) : "l"(a), "l"(b));
    return d;
}
__device__ __forceinline__ u64 dup2(float x) {
    u64 d;
    unsigned u = __float_as_uint(x);
    asm("mov.b64 %0, {%1, %1};" : "=l"(d) : "r"(u));
    return d;
}
__device__ __forceinline__ u64 pack2(float lo, float hi) {
    u64 d;
    asm("mov.b64 %0, {%1, %2};" : "=l"(d) : "r"(__float_as_uint(lo)), "r"(__float_as_uint(hi)));
    return d;
}
__device__ __forceinline__ void unpack2(u64 p, float& lo, float& hi) {
    unsigned a, b;
    asm("mov.b64 {%0, %1}, %2;" : "=r"(a), "=r"(b) : "l"(p));
    lo = __uint_as_float(a);
    hi = __uint_as_float(b);
}

// ---------------- per-head relative-bias table ----------------
// rp = k - q in [-1023, 1023]; table[h][rp+1023] = rel_embed[bucket(rp)][h]
__global__ void rel_kernel(const float* __restrict__ rel_embed) {
    int h = blockIdx.x;
    for (int i = threadIdx.x; i < 2047; i += blockDim.x) {
        int rp = i - 1023;
        int ret = (rp > 0) ? 160 : 0;
        int arp = rp < 0 ? -rp : rp;
        int bb;
        if (arp < 80) {
            bb = arp;
        } else {
            // match jnp op order: log(|rp|/80)/log(800/80)*80, trunc after +80
            float l = logf((float)arp / 80.0f);
            l = l * (1.0f / 2.302585092994046f);
            l = l * 80.0f;
            bb = (int)(80.0f + l);
            if (bb > 159) bb = 159;
        }
        g_relb[h*2048 + i] = rel_embed[(ret + bb)*H_ + h];
    }
}

// ---------------- gate: one warp per (b,h,t) ----------------
__global__ void gate_kernel(const float* __restrict__ hs,
                            const float* __restrict__ gw,
                            const float* __restrict__ gb,
                            const float* __restrict__ gc) {
    int warp = (blockIdx.x * blockDim.x + threadIdx.x) >> 5;
    int lane = threadIdx.x & 31;
    if (warp >= B_*H_*T_) return;
    int h = (warp >> 10) & 15;
    int b = warp >> 14;
    int t = warp & 1023;
    const float* x = hs + ((size_t)(b*T_ + t))*D_ + h*HD;
    float x0 = x[lane];
    float x1 = x[lane + 32];
    float acc[8];
#pragma unroll
    for (int e = 0; e < 8; e++)
        acc[e] = x0 * gw[e*HD + lane] + x1 * gw[e*HD + lane + 32];
#pragma unroll
    for (int e = 0; e < 8; e++)
#pragma unroll
        for (int o = 16; o > 0; o >>= 1)
            acc[e] += __shfl_xor_sync(0xffffffffu, acc[e], o);
    if (lane == 0) {
        float pa = acc[0]+acc[1]+acc[2]+acc[3] + gb[0]+gb[1]+gb[2]+gb[3];
        float pb = acc[4]+acc[5]+acc[6]+acc[7] + gb[4]+gb[5]+gb[6]+gb[7];
        float ga  = 1.0f / (1.0f + expf(-pa));
        float gbs = 1.0f / (1.0f + expf(-pb));
        float c = gc[h];
        g_gate[warp] = ga * (gbs * c - 1.0f) + 2.0f;
    }
}

// ---------------- fp32 GEMM body: C = (A @ W^T + bias)*scale ----------------
// A: [M,1024] row-major, W: [1024,1024] row-major (both K-contiguous).
// Inner loop uses packed f32x2 FMA (2 FLOPs/lane/issue).
// mode 0: C[m*1024+n]. mode 1: qkv head layout dst[((b*16+h)*1024+t)*64+d].
#define BM 128
#define BN 128
#define BK 16

__device__ __forceinline__
void gemm_body(const float* __restrict__ A, const float* __restrict__ W,
               const float* __restrict__ bias, float* __restrict__ C,
               float scale, int mode, int m0, int n0) {
    // 16B-aligned bases; row stride (BM+4)=132 floats = 528B, multiple of 16.
    __shared__ __align__(16) float As[BK][BM + 4];
    __shared__ __align__(16) float Bs[BK][BN + 4];
    const int K = 1024;
    int tid = threadIdx.x;
    int tx = tid & 15, ty = tid >> 4;

    int r0 = tid >> 2;               // 0..63
    int c4 = (tid & 3) * 4;          // 0,4,8,12
    const float* pa0 = A + (size_t)(m0 + r0)*K + c4;
    const float* pa1 = A + (size_t)(m0 + r0 + 64)*K + c4;
    const float* pw0 = W + (size_t)(n0 + r0)*K + c4;
    const float* pw1 = W + (size_t)(n0 + r0 + 64)*K + c4;

    u64 acc2[8][4];
#pragma unroll
    for (int i = 0; i < 8; i++)
#pragma unroll
        for (int j = 0; j < 4; j++) acc2[i][j] = 0ull;

    float4 a0 = *(const float4*)(pa0);
    float4 a1 = *(const float4*)(pa1);
    float4 w0 = *(const float4*)(pw0);
    float4 w1 = *(const float4*)(pw1);

    for (int k0 = 0; k0 < K; k0 += BK) {
        As[c4+0][r0]    = a0.x; As[c4+1][r0]    = a0.y;
        As[c4+2][r0]    = a0.z; As[c4+3][r0]    = a0.w;
        As[c4+0][r0+64] = a1.x; As[c4+1][r0+64] = a1.y;
        As[c4+2][r0+64] = a1.z; As[c4+3][r0+64] = a1.w;
        Bs[c4+0][r0]    = w0.x; Bs[c4+1][r0]    = w0.y;
        Bs[c4+2][r0]    = w0.z; Bs[c4+3][r0]    = w0.w;
        Bs[c4+0][r0+64] = w1.x; Bs[c4+1][r0+64] = w1.y;
        Bs[c4+2][r0+64] = w1.z; Bs[c4+3][r0+64] = w1.w;
        __syncthreads();

        if (k0 + BK < K) {
            a0 = *(const float4*)(pa0 + k0 + BK);
            a1 = *(const float4*)(pa1 + k0 + BK);
            w0 = *(const float4*)(pw0 + k0 + BK);
            w1 = *(const float4*)(pw1 + k0 + BK);
        }

#pragma unroll
        for (int kk = 0; kk < BK; kk++) {
            float af[8];
            *(float4*)&af[0] = *(const float4*)&As[kk][ty*8];
            *(float4*)&af[4] = *(const float4*)&As[kk][ty*8 + 4];
            u64 b2[4];
            {
                ulonglong2 p = *(const ulonglong2*)&Bs[kk][tx*8];
                ulonglong2 q = *(const ulonglong2*)&Bs[kk][tx*8 + 4];
                b2[0] = p.x; b2[1] = p.y; b2[2] = q.x; b2[3] = q.y;
            }
#pragma unroll
            for (int i = 0; i < 8; i++) {
                u64 ad = dup2(af[i]);
#pragma unroll
                for (int j = 0; j < 4; j++)
                    acc2[i][j] = fma2(ad, b2[j], acc2[i][j]);
            }
        }
        __syncthreads();
    }

    // epilogue: each row i owns 8 contiguous output cols starting at n0+tx*8.
    // 8-aligned blocks never straddle a 64 (head) boundary -> 2x STG.128.
    int nbase = n0 + tx*8;
    float4 bias_lo = *(const float4*)(bias + nbase);
    float4 bias_hi = *(const float4*)(bias + nbase + 4);
#pragma unroll
    for (int i = 0; i < 8; i++) {
        int m = m0 + ty*8 + i;
        float v[8];
        unpack2(acc2[i][0], v[0], v[1]);
        unpack2(acc2[i][1], v[2], v[3]);
        unpack2(acc2[i][2], v[4], v[5]);
        unpack2(acc2[i][3], v[6], v[7]);
        float4 lo, hi;
        lo.x = (v[0] + bias_lo.x) * scale;
        lo.y = (v[1] + bias_lo.y) * scale;
        lo.z = (v[2] + bias_lo.z) * scale;
        lo.w = (v[3] + bias_lo.w) * scale;
        hi.x = (v[4] + bias_hi.x) * scale;
        hi.y = (v[5] + bias_hi.y) * scale;
        hi.z = (v[6] + bias_hi.z) * scale;
        hi.w = (v[7] + bias_hi.w) * scale;
        float* dst;
        if (mode == 0) {
            dst = C + (size_t)m*1024 + nbase;
        } else {
            int b = m >> 10, t = m & 1023;
            int h = nbase >> 6, d = nbase & 63;
            dst = C + (((size_t)(b*16 + h))*1024 + t)*64 + d;
        }
        *(float4*)(dst)     = lo;
        *(float4*)(dst + 4) = hi;
    }
}

__global__ __launch_bounds__(256, 2)
void sgemm_nt(const float* __restrict__ A, const float* __restrict__ W,
              const float* __restrict__ bias, float* __restrict__ C,
              float scale, int mode) {
    gemm_body(A, W, bias, C, scale, mode, blockIdx.y * BM, blockIdx.x * BN);
}

__global__ __launch_bounds__(256, 2)
void sgemm_qkv(const float* __restrict__ A,
               const float* __restrict__ qw, const float* __restrict__ qb,
               const float* __restrict__ kw, const float* __restrict__ kb,
               const float* __restrict__ vw, const float* __restrict__ vb,
               float* __restrict__ qo, float* __restrict__ ko,
               float* __restrict__ vo) {
    int z = blockIdx.z;
    const float* W    = (z == 0) ? qw : (z == 1) ? kw : vw;
    const float* bias = (z == 0) ? qb : (z == 1) ? kb : vb;
    float*       C    = (z == 0) ? qo : (z == 1) ? ko : vo;
    float scale       = (z == 0) ? 0.125f : 1.0f;   // hd^-0.5
    gemm_body(A, W, bias, C, scale, 1, blockIdx.y * BM, blockIdx.x * BN);
}

// ---------------- flash attention with gated relative bias ----------------
// grid: (16 qtiles, 16 heads, 4 batch). 256 threads, 4x4 micro-tile on 64x64.
// K stored TRANSPOSED in smem (Ks[d][k]) -> packed f32x2 FMA in both matmuls.
// K/V tiles are register-staged: next tile's LDGs issue right after the
// store-phase sync so their latency hides behind S/softmax/PV compute.
// Bias: smem band relb[s], s = kglob - qloc + 63.
// SROW = 68: row stride 272B = multiple of 16 -> every float4/ulonglong2
// smem access is 16B-aligned for ALL rows (66/65 were misaligned for odd rows).
#define SROW 68

__global__ __launch_bounds__(256)
void flash_kernel() {
    extern __shared__ __align__(16) float sm[];
    float* Qs   = sm;                 // [64][SROW]  q-row major
    float* Ks   = Qs + 64*SROW;       // [64][SROW]  TRANSPOSED: d-row, k-col
    float* Vs   = Ks + 64*SROW;       // [64][SROW]  k-row major
    float* Ps   = Vs + 64*SROW;       // [64][SROW]  q-row major
    float* relb = Ps + 64*SROW;       // 1088 floats: bias band for this block

    int qt = blockIdx.x, h = blockIdx.y, b = blockIdx.z;
    int q0 = qt * 64;
    int tid = threadIdx.x;
    int tx = tid & 15, ty = tid >> 4;
    size_t base = ((size_t)(b*H_ + h)) * T_ * HD;

    // per-thread load slots (same mapping for all 4 chunks)
    int lr[4], lc[4];
#pragma unroll
    for (int li = 0; li < 4; li++) {
        int idx = li*256 + tid;
        lr[li] = idx >> 4;            // row (k index)
        lc[li] = (idx & 15) * 4;      // col (d base)
    }

    // load bias band: relb[s] = table[s + 960 - q0]
    {
        const float* tab = g_relb + h*2048;
        for (int s = tid; s < 1088; s += 256) {
            int gidx = s + 960 - q0;
            gidx = gidx < 0 ? 0 : (gidx > 2046 ? 2046 : gidx);
            relb[s] = tab[gidx];
        }
    }

    // load Q tile (64x64) into smem
#pragma unroll
    for (int li = 0; li < 4; li++) {
        float4 qv = *(const float4*)(g_q + base + (size_t)(q0 + lr[li])*64 + lc[li]);
        int r = lr[li], c = lc[li];
        Qs[r*SROW + c + 0] = qv.x; Qs[r*SROW + c + 1] = qv.y;
        Qs[r*SROW + c + 2] = qv.z; Qs[r*SROW + c + 3] = qv.w;
    }

    float gate_r[4];
#pragma unroll
    for (int i = 0; i < 4; i++)
        gate_r[i] = g_gate[(b*H_ + h)*T_ + q0 + ty*4 + i];

    float m_i[4], l_i[4];
    u64 o2[4][2];                      // packed output accum: [qrow][dpair]
#pragma unroll
    for (int i = 0; i < 4; i++) {
        m_i[i] = -INFINITY; l_i[i] = 0.0f;
        o2[i][0] = 0ull; o2[i][1] = 0ull;
    }

    // prologue: stage k-tile 0 of K and V into registers
    float4 kreg[4], vreg[4];
#pragma unroll
    for (int li = 0; li < 4; li++) {
        kreg[li] = *(const float4*)(g_k + base + (size_t)lr[li]*64 + lc[li]);
        vreg[li] = *(const float4*)(g_v + base + (size_t)lr[li]*64 + lc[li]);
    }
    __syncthreads();

    for (int kt = 0; kt < 16; kt++) {
        // store staged registers to smem (K transposed, V straight)
#pragma unroll
        for (int li = 0; li < 4; li++) {
            int r = lr[li], c = lc[li];
            Ks[(c+0)*SROW + r] = kreg[li].x; Ks[(c+1)*SROW + r] = kreg[li].y;
            Ks[(c+2)*SROW + r] = kreg[li].z; Ks[(c+3)*SROW + r] = kreg[li].w;
            Vs[r*SROW + c + 0] = vreg[li].x; Vs[r*SROW + c + 1] = vreg[li].y;
            Vs[r*SROW + c + 2] = vreg[li].z; Vs[r*SROW + c + 3] = vreg[li].w;
        }
        __syncthreads();

        // prefetch next k-tile while computing this one
        if (kt + 1 < 16) {
            size_t nb = base + (size_t)(kt + 1)*64*64;
#pragma unroll
            for (int li = 0; li < 4; li++) {
                kreg[li] = *(const float4*)(g_k + nb + (size_t)lr[li]*64 + lc[li]);
                vreg[li] = *(const float4*)(g_v + nb + (size_t)lr[li]*64 + lc[li]);
            }
        }

        int k0 = kt * 64;
        // S = Q @ K^T + gate*relbias : packed over k-pairs
        u64 s2[4][2];
        {
            int sb = k0 + tx*4 + 63 - ty*4;   // s for (i=0, j=0)
#pragma unroll
            for (int i = 0; i < 4; i++) {
                const float* rb = relb + (sb - i);
                float g = gate_r[i];
                s2[i][0] = pack2(g*rb[0], g*rb[1]);
                s2[i][1] = pack2(g*rb[2], g*rb[3]);
            }
        }
#pragma unroll 8
        for (int d = 0; d < 64; d++) {
            // this thread's 4 k-columns are contiguous in transposed Ks
            ulonglong2 kp = *(const ulonglong2*)&Ks[d*SROW + tx*4];
#pragma unroll
            for (int i = 0; i < 4; i++) {
                u64 qd = dup2(Qs[(ty*4 + i)*SROW + d]);
                s2[i][0] = fma2(qd, kp.x, s2[i][0]);
                s2[i][1] = fma2(qd, kp.y, s2[i][1]);
            }
        }

        // online softmax (row spread across 16 tx lanes within half-warp)
#pragma unroll
        for (int i = 0; i < 4; i++) {
            float s0, s1, s2a, s3;
            unpack2(s2[i][0], s0, s1);
            unpack2(s2[i][1], s2a, s3);
            float rm = fmaxf(fmaxf(s0, s1), fmaxf(s2a, s3));
#pragma unroll
            for (int off = 8; off > 0; off >>= 1)
                rm = fmaxf(rm, __shfl_xor_sync(0xffffffffu, rm, off, 16));
            float mnew = fmaxf(m_i[i], rm);
            float alpha = __expf(m_i[i] - mnew);
            m_i[i] = mnew;
            float e0 = __expf(s0 - mnew), e1 = __expf(s1 - mnew);
            float e2 = __expf(s2a - mnew), e3 = __expf(s3 - mnew);
            float rs = (e0 + e1) + (e2 + e3);
#pragma unroll
            for (int off = 8; off > 0; off >>= 1)
                rs += __shfl_xor_sync(0xffffffffu, rs, off, 16);
            l_i[i] = l_i[i] * alpha + rs;
            u64 ad = dup2(alpha);
            o2[i][0] = mul2(o2[i][0], ad);
            o2[i][1] = mul2(o2[i][1], ad);
            // packed store of probabilities (16B-aligned with SROW=68)
            *(u64*)&Ps[(ty*4 + i)*SROW + tx*4]     = pack2(e0, e1);
            *(u64*)&Ps[(ty*4 + i)*SROW + tx*4 + 2] = pack2(e2, e3);
        }
        __syncthreads();

        // O += P @ V : packed over d-pairs
#pragma unroll 8
        for (int kk = 0; kk < 64; kk++) {
            ulonglong2 vp = *(const ulonglong2*)&Vs[kk*SROW + tx*4];
#pragma unroll
            for (int i = 0; i < 4; i++) {
                u64 pd = dup2(Ps[(ty*4 + i)*SROW + kk]);
                o2[i][0] = fma2(pd, vp.x, o2[i][0]);
                o2[i][1] = fma2(pd, vp.y, o2[i][1]);
            }
        }
        __syncthreads();
    }

    // write ctx in [B,T,D] layout (4 contiguous floats -> STG.128)
#pragma unroll
    for (int i = 0; i < 4; i++) {
        int t = q0 + ty*4 + i;
        float inv_l = 1.0f / l_i[i];
        float4 out;
        unpack2(o2[i][0], out.x, out.y);
        unpack2(o2[i][1], out.z, out.w);
        out.x *= inv_l; out.y *= inv_l; out.z *= inv_l; out.w *= inv_l;
        *(float4*)(g_ctx + ((size_t)(b*T_ + t))*D_ + h*HD + tx*4) = out;
    }
}

// ---------------- launch ----------------
extern "C" void kernel_launch(void* const* d_in, const int* in_sizes, int n_in,
                              void* d_out, int out_size) {
    const float* hs        = (const float*)d_in[0];
    const float* q_w       = (const float*)d_in[1];
    const float* q_b       = (const float*)d_in[2];
    const float* k_w       = (const float*)d_in[3];
    const float* k_b       = (const float*)d_in[4];
    const float* v_w       = (const float*)d_in[5];
    const float* v_b       = (const float*)d_in[6];
    const float* out_w     = (const float*)d_in[7];
    const float* out_b     = (const float*)d_in[8];
    const float* rel_embed = (const float*)d_in[9];
    const float* gru_const = (const float*)d_in[10];
    const float* gru_w     = (const float*)d_in[11];
    const float* gru_b     = (const float*)d_in[12];

    float *qp, *kp, *vp, *ctxp;
    cudaGetSymbolAddress((void**)&qp,   g_q);
    cudaGetSymbolAddress((void**)&kp,   g_k);
    cudaGetSymbolAddress((void**)&vp,   g_v);
    cudaGetSymbolAddress((void**)&ctxp, g_ctx);

    rel_kernel<<<H_, 256>>>(rel_embed);
    gate_kernel<<<(B_*H_*T_)/8, 256>>>(hs, gru_w, gru_b, gru_const);

    sgemm_qkv<<<dim3(8, 32, 3), 256>>>(hs, q_w, q_b, k_w, k_b, v_w, v_b,
                                       qp, kp, vp);

    size_t shmem = (size_t)(4*64*SROW + 1088) * sizeof(float);
    cudaFuncSetAttribute(flash_kernel,
                         cudaFuncAttributeMaxDynamicSharedMemorySize, (int)shmem);
    flash_kernel<<<dim3(16, 16, 4), 256, shmem>>>();

    sgemm_nt<<<dim3(8, 32), 256>>>(ctxp, out_w, out_b, (float*)d_out, 1.0f, 0);
}